// round 10
// baseline (speedup 1.0000x reference)
#include <cuda_runtime.h>
#include <cuda_bf16.h>
#include <cstdint>

using bf16 = __nv_bfloat16;

static constexpr int BB   = 4;
static constexpr int NN   = 4096;          // H*W
static constexpr int CC   = 512;
static constexpr int C8   = 64;            // q/k dim
static constexpr int C2   = 256;           // v dim
static constexpr int MT   = BB * NN;       // 16384
static constexpr int NCAT = C8 + C8 + C2;  // 384

// ---------------- scratch (__device__ globals: allocation-free) ----------------
__device__ bf16  g_Xb[(size_t)MT * CC];         // x in bf16
__device__ bf16  g_Wcat[(size_t)CC * NCAT];     // [Wf|Wg|Wh] bf16
__device__ float g_bcat[NCAT];
__device__ bf16  g_Wob[(size_t)C2 * CC];        // Wo bf16
__device__ bf16  g_Q[(size_t)MT * C8];          // "g" (queries), [b*N][64]
__device__ bf16  g_Kt[(size_t)BB * C8 * NN];    // "f" transposed, [b][64][N]
__device__ bf16  g_V[(size_t)MT * C2];          // "h" (values), [b*N][256]
__device__ float g_S[(size_t)BB * NN * NN];     // logits fp32 (256 MB)
__device__ bf16  g_P[(size_t)BB * NN * NN];     // softmax probs bf16 (128 MB)
__device__ bf16  g_O[(size_t)MT * C2];          // attention output bf16

// ---------------- PTX helpers ----------------
#define CP_ASYNC16(dst, src) \
  asm volatile("cp.async.cg.shared.global [%0], [%1], 16;\n" :: "r"(dst), "l"(src))

#define MMA_BF16(D, A, B0, B1)                                              \
  asm volatile("mma.sync.aligned.m16n8k16.row.col.f32.bf16.bf16.f32 "       \
    "{%0,%1,%2,%3}, {%4,%5,%6,%7}, {%8,%9}, {%0,%1,%2,%3};"                 \
    : "+f"((D)[0]), "+f"((D)[1]), "+f"((D)[2]), "+f"((D)[3])                \
    : "r"((A)[0]), "r"((A)[1]), "r"((A)[2]), "r"((A)[3]), "r"(B0), "r"(B1))

// ---------------- prep kernels ----------------
__global__ void convert_x_kernel(const float* __restrict__ x) {
    int i = blockIdx.x * blockDim.x + threadIdx.x;
    const int n = MT * CC;
    const int stride = gridDim.x * blockDim.x;
    for (; i < n; i += stride) g_Xb[i] = __float2bfloat16(x[i]);
}

__global__ void prep_weights_kernel(const float* __restrict__ Wf, const float* __restrict__ bfv,
                                    const float* __restrict__ Wg, const float* __restrict__ bgv,
                                    const float* __restrict__ Wh, const float* __restrict__ bhv,
                                    const float* __restrict__ Wo) {
    int i = blockIdx.x * blockDim.x + threadIdx.x;
    if (i < CC * NCAT) {
        int k = i / NCAT, c = i % NCAT;
        float v = (c < C8)     ? Wf[k * C8 + c]
                : (c < 2 * C8) ? Wg[k * C8 + (c - C8)]
                               : Wh[k * C2 + (c - 2 * C8)];
        g_Wcat[i] = __float2bfloat16(v);
    }
    if (i < NCAT) {
        g_bcat[i] = (i < C8) ? bfv[i] : (i < 2 * C8) ? bgv[i - C8] : bhv[i - 2 * C8];
    }
    if (i < C2 * CC) g_Wob[i] = __float2bfloat16(Wo[i]);
}

// ---------------- epilogue dispatch ----------------
// EPI 0: projection (bias add, split into Kt/Q/V, bf16)
// EPI 1: S fp32 write
// EPI 2: O bf16 write
// EPI 3: out = gamma*(acc+bo) + x   (fp32)
template<int EPI>
__device__ __forceinline__ void epi_write(int bz, int r, int c, float v0, float v1,
                                          const float* xres, const float* bias_in,
                                          const float* gamma, float* out) {
    if constexpr (EPI == 0) {
        v0 += g_bcat[c]; v1 += g_bcat[c + 1];
        int b = r >> 12, np = r & (NN - 1);
        if (c < C8) {
            g_Kt[((size_t)b * C8 + c)     * NN + np] = __float2bfloat16(v0);
            g_Kt[((size_t)b * C8 + c + 1) * NN + np] = __float2bfloat16(v1);
        } else if (c < 2 * C8) {
            g_Q[(size_t)r * C8 + (c - C8)]     = __float2bfloat16(v0);
            g_Q[(size_t)r * C8 + (c - C8 + 1)] = __float2bfloat16(v1);
        } else {
            g_V[(size_t)r * C2 + (c - 2 * C8)]     = __float2bfloat16(v0);
            g_V[(size_t)r * C2 + (c - 2 * C8 + 1)] = __float2bfloat16(v1);
        }
    } else if constexpr (EPI == 1) {
        float* dst = g_S + (size_t)bz * NN * NN + (size_t)r * NN + c;
        dst[0] = v0; dst[1] = v1;
    } else if constexpr (EPI == 2) {
        bf16* dst = g_O + (size_t)bz * NN * C2 + (size_t)r * C2 + c;
        dst[0] = __float2bfloat16(v0); dst[1] = __float2bfloat16(v1);
    } else {
        float gm = gamma[0];
        size_t i = (size_t)r * CC + c;
        out[i]     = gm * (v0 + bias_in[c])     + xres[i];
        out[i + 1] = gm * (v1 + bias_in[c + 1]) + xres[i + 1];
    }
}

// ---------------- generic bf16 GEMM: C[M,N] = A[M,K] @ B[K,N] ----------------
// 128x128x32 CTA tile, 8 warps (4 along M x 2 along N), warp tile 32x64,
// mma.m16n8k16, cp.async double buffer, padded smem + ldmatrix.
template<int EPI, int M, int N, int K, int LDA, int LDB>
__global__ void __launch_bounds__(256) gemm_kernel(const float* __restrict__ xres,
                                                   const float* __restrict__ bias_in,
                                                   const float* __restrict__ gamma,
                                                   float* __restrict__ out) {
    constexpr int BM = 128, BN = 128, BK = 32;
    constexpr int AST = BK + 8;   // 40 elems/row (80B, 16B-aligned, conflict-free ldmatrix)
    constexpr int BST = BN + 8;   // 136 elems/row (272B)
    __shared__ __align__(16) bf16 As[2][BM][AST];
    __shared__ __align__(16) bf16 Bs[2][BK][BST];

    const int tid = threadIdx.x;
    const int bz  = blockIdx.z;
    const int rowBase = blockIdx.y * BM;
    const int colBase = blockIdx.x * BN;

    const bf16* Ag; const bf16* Bg;
    if constexpr (EPI == 0)      { Ag = g_Xb;                       Bg = g_Wcat; }
    else if constexpr (EPI == 1) { Ag = g_Q + (size_t)bz * NN * C8; Bg = g_Kt + (size_t)bz * C8 * NN; }
    else if constexpr (EPI == 2) { Ag = g_P + (size_t)bz * NN * NN; Bg = g_V  + (size_t)bz * NN * C2; }
    else                         { Ag = g_O;                        Bg = g_Wob; }

    const uint32_t sAb = (uint32_t)__cvta_generic_to_shared(&As[0][0][0]);
    const uint32_t sBb = (uint32_t)__cvta_generic_to_shared(&Bs[0][0][0]);
    constexpr uint32_t ASTAGE = BM * AST * 2;
    constexpr uint32_t BSTAGE = BK * BST * 2;

    // per-thread gmem->smem chunk coords (16B cp.async)
    const int la_r = tid >> 2;            // 0..63 (rows r and r+64)
    const int la_c = (tid & 3) << 3;      // 0,8,16,24
    const int lb_r = tid >> 4;            // 0..15 (rows r and r+16)
    const int lb_c = (tid & 15) << 3;     // 0..120

    auto load_tile = [&](int kt, int b) {
        const bf16* a0 = Ag + (size_t)(rowBase + la_r) * LDA + kt * BK + la_c;
        uint32_t d0 = sAb + (uint32_t)b * ASTAGE + (uint32_t)(la_r * AST + la_c) * 2;
        CP_ASYNC16(d0, a0);
        CP_ASYNC16(d0 + 64u * AST * 2, a0 + (size_t)64 * LDA);
        const bf16* b0 = Bg + (size_t)(kt * BK + lb_r) * LDB + colBase + lb_c;
        uint32_t e0 = sBb + (uint32_t)b * BSTAGE + (uint32_t)(lb_r * BST + lb_c) * 2;
        CP_ASYNC16(e0, b0);
        CP_ASYNC16(e0 + 16u * BST * 2, b0 + (size_t)16 * LDB);
        asm volatile("cp.async.commit_group;\n");
    };

    float acc[2][8][4];
    #pragma unroll
    for (int i = 0; i < 2; i++)
        #pragma unroll
        for (int j = 0; j < 8; j++)
            #pragma unroll
            for (int q = 0; q < 4; q++) acc[i][j][q] = 0.f;

    const int warp = tid >> 5, lane = tid & 31;
    const int wm = warp & 3, wn = warp >> 2;   // 4 x 2 warp grid

    constexpr int KT = K / BK;
    load_tile(0, 0);
    int buf = 0;
    #pragma unroll 1
    for (int kt = 0; kt < KT; ++kt) {
        if (kt + 1 < KT) {
            load_tile(kt + 1, buf ^ 1);
            asm volatile("cp.async.wait_group 1;\n");
        } else {
            asm volatile("cp.async.wait_group 0;\n");
        }
        __syncthreads();
        #pragma unroll
        for (int ks = 0; ks < 2; ++ks) {           // two k16 steps per BK=32
            uint32_t a[2][4];
            #pragma unroll
            for (int mi = 0; mi < 2; ++mi) {
                int row = wm * 32 + mi * 16 + (lane & 15);
                int col = ks * 16 + ((lane >> 4) << 3);
                uint32_t addr = sAb + (uint32_t)buf * ASTAGE + (uint32_t)(row * AST + col) * 2;
                asm volatile("ldmatrix.sync.aligned.m8n8.x4.shared.b16 {%0,%1,%2,%3}, [%4];"
                    : "=r"(a[mi][0]), "=r"(a[mi][1]), "=r"(a[mi][2]), "=r"(a[mi][3]) : "r"(addr));
            }
            #pragma unroll
            for (int nj = 0; nj < 4; ++nj) {        // 4 x n16 blocks = 64 cols
                int krow = ks * 16 + (lane & 15);
                int col  = wn * 64 + nj * 16 + ((lane >> 4) << 3);
                uint32_t addr = sBb + (uint32_t)buf * BSTAGE + (uint32_t)(krow * BST + col) * 2;
                uint32_t b0, b1, b2, b3;
                asm volatile("ldmatrix.sync.aligned.m8n8.x4.trans.shared.b16 {%0,%1,%2,%3}, [%4];"
                    : "=r"(b0), "=r"(b1), "=r"(b2), "=r"(b3) : "r"(addr));
                #pragma unroll
                for (int mi = 0; mi < 2; ++mi) {
                    MMA_BF16(acc[mi][2 * nj],     a[mi], b0, b1);
                    MMA_BF16(acc[mi][2 * nj + 1], a[mi], b2, b3);
                }
            }
        }
        __syncthreads();
        buf ^= 1;
    }

    // epilogue: m16n8 accum layout -> (row lane/4 [,+8], col (lane&3)*2 [,+1])
    const int row0 = rowBase + wm * 32;
    const int col0 = colBase + wn * 64;
    #pragma unroll
    for (int mi = 0; mi < 2; ++mi) {
        #pragma unroll
        for (int nj = 0; nj < 8; ++nj) {
            int r = row0 + mi * 16 + (lane >> 2);
            int c = col0 + nj * 8 + ((lane & 3) << 1);
            epi_write<EPI>(bz, r,     c, acc[mi][nj][0], acc[mi][nj][1], xres, bias_in, gamma, out);
            epi_write<EPI>(bz, r + 8, c, acc[mi][nj][2], acc[mi][nj][3], xres, bias_in, gamma, out);
        }
    }
}

// ---------------- softmax over rows of S (4096 wide), write bf16 P ----------------
__global__ void __launch_bounds__(256) softmax_kernel() {
    const size_t row = blockIdx.x;
    const float* s = g_S + row * NN;
    bf16* p = g_P + row * NN;
    const int t = threadIdx.x;

    float v[16];
    float m = -1e30f;
    #pragma unroll
    for (int i = 0; i < 16; i++) { v[i] = s[t + 256 * i]; m = fmaxf(m, v[i]); }

    __shared__ float red[8];
    __shared__ float red2[8];
    #pragma unroll
    for (int o = 16; o > 0; o >>= 1) m = fmaxf(m, __shfl_xor_sync(0xffffffffu, m, o));
    if ((t & 31) == 0) red[t >> 5] = m;
    __syncthreads();
    float gm = red[0];
    #pragma unroll
    for (int i = 1; i < 8; i++) gm = fmaxf(gm, red[i]);

    float sum = 0.f;
    #pragma unroll
    for (int i = 0; i < 16; i++) { v[i] = __expf(v[i] - gm); sum += v[i]; }
    #pragma unroll
    for (int o = 16; o > 0; o >>= 1) sum += __shfl_xor_sync(0xffffffffu, sum, o);
    __syncthreads();
    if ((t & 31) == 0) red2[t >> 5] = sum;
    __syncthreads();
    float tot = 0.f;
    #pragma unroll
    for (int i = 0; i < 8; i++) tot += red2[i];
    float inv = 1.f / tot;
    #pragma unroll
    for (int i = 0; i < 16; i++) p[t + 256 * i] = __float2bfloat16(v[i] * inv);
}

// ---------------- launcher ----------------
extern "C" void kernel_launch(void* const* d_in, const int* in_sizes, int n_in,
                              void* d_out, int out_size) {
    (void)in_sizes; (void)n_in; (void)out_size;
    const float* x    = (const float*)d_in[0];
    const float* Wf   = (const float*)d_in[1];
    const float* bfv  = (const float*)d_in[2];
    const float* Wg   = (const float*)d_in[3];
    const float* bgv  = (const float*)d_in[4];
    const float* Wh   = (const float*)d_in[5];
    const float* bhv  = (const float*)d_in[6];
    const float* Wo   = (const float*)d_in[7];
    const float* bo   = (const float*)d_in[8];
    const float* gamma = (const float*)d_in[9];
    float* out = (float*)d_out;

    // prep: x -> bf16; weights -> bf16 (Wcat = [Wf|Wg|Wh], bcat, Wo)
    convert_x_kernel<<<8192, 256>>>(x);
    prep_weights_kernel<<<768, 256>>>(Wf, bfv, Wg, bgv, Wh, bhv, Wo);

    // projections: [16384,512] @ [512,384] -> Kt / Q / V (bias fused)
    gemm_kernel<0, MT, NCAT, CC, CC, NCAT>
        <<<dim3(NCAT / 128, MT / 128, 1), 256>>>(nullptr, nullptr, nullptr, nullptr);

    // S = Q @ Kt : per-batch [4096,64] @ [64,4096] -> fp32 logits
    gemm_kernel<1, NN, NN, C8, C8, NN>
        <<<dim3(NN / 128, NN / 128, BB), 256>>>(nullptr, nullptr, nullptr, nullptr);

    // softmax rows -> P (bf16)
    softmax_kernel<<<BB * NN, 256>>>();

    // O = P @ V : per-batch [4096,4096] @ [4096,256] -> bf16
    gemm_kernel<2, NN, C2, NN, NN, C2>
        <<<dim3(C2 / 128, NN / 128, BB), 256>>>(nullptr, nullptr, nullptr, nullptr);

    // out = gamma * (O @ Wo + bo) + x
    gemm_kernel<3, MT, CC, C2, C2, CC>
        <<<dim3(CC / 128, MT / 128, 1), 256>>>(x, bo, gamma, out);
}